// round 13
// baseline (speedup 1.0000x reference)
#include <cuda_runtime.h>
#include <cuda_bf16.h>
#include <cuda_fp16.h>

// CasamentoMult on GB300 — R9 (f16x2 MUFU) with the stalls engineered out:
// 6 rotating half2 accumulators, MUFUs batched back-to-back per pair,
// occupancy held at >=5 blocks/SM.
// sigma = 1/sqrt(2*pi) => log_sqrt_pi == 0; pair term = exp(-pi*diff^2)
//   = 2^(NSC2*diff^2), NSC2 = -pi*log2(e).  Collapsed form:
//  total = NE + sum_k [ 0.5*(gy+gd-c1-c2) - s ]
//             + 0.5*e(d[0]-y[0]) - 0.5*e(d[NE]-y[NE]),   NE = N-2.

#define NBLK 1184          // 148 SMs * 8 requested
#define NTHR 256

__device__ float    g_partials[NBLK];
__device__ unsigned g_ticket = 0;

#define SC    2.1289340388624523f   // sqrt(pi*log2(e))  (scalar tail path)
#define NSC2f -4.532360141827194f   // -pi*log2(e)

// ---- f32x2 helpers (double containers; FP64 pipe never used) ----
__device__ __forceinline__ double pk2(float lo, float hi) {
    double r; asm("mov.b64 %0, {%1, %2};" : "=d"(r) : "f"(lo), "f"(hi)); return r;
}
__device__ __forceinline__ float lo2(double v) {
    return __uint_as_float((unsigned)__double2loint(v));
}
__device__ __forceinline__ float hi2(double v) {
    return __uint_as_float((unsigned)__double2hiint(v));
}
__device__ __forceinline__ double sub2(double a, double b) {   // a - b
    double r; asm("sub.rn.f32x2 %0, %1, %2;" : "=d"(r) : "d"(a), "d"(b)); return r;
}
__device__ __forceinline__ double mul2(double a, double b) {
    double r; asm("mul.rn.f32x2 %0, %1, %2;" : "=d"(r) : "d"(a), "d"(b)); return r;
}

// pack the two f32 halves of nv into one f16x2 register
__device__ __forceinline__ unsigned h2of(double nv) {
    float flo, fhi; unsigned h;
    asm("mov.b64 {%0, %1}, %2;" : "=f"(flo), "=f"(fhi) : "d"(nv));
    asm("cvt.rn.f16x2.f32 %0, %1, %2;" : "=r"(h) : "f"(fhi), "f"(flo));
    return h;
}
__device__ __forceinline__ unsigned hex2(unsigned h) {         // 2^h, both halves
    unsigned r; asm("ex2.approx.f16x2 %0, %1;" : "=r"(r) : "r"(h)); return r;
}
__device__ __forceinline__ unsigned hadd2(unsigned a, unsigned b) {
    unsigned r; asm("add.rn.f16x2 %0, %1, %2;" : "=r"(r) : "r"(a), "r"(b)); return r;
}
__device__ __forceinline__ float h2sum(unsigned h) {           // lo+hi as float
    float lo, hi;
    asm("{\n\t.reg .f16 l, g;\n\tmov.b32 {l, g}, %2;\n\t"
        "cvt.f32.f16 %0, l;\n\tcvt.f32.f16 %1, g;\n\t}"
        : "=f"(lo), "=f"(hi) : "r"(h));
    return lo + hi;
}

__device__ __forceinline__ float ex2f(float a) {
    float r; asm("ex2.approx.f32 %0, %1;" : "=f"(r) : "f"(a)); return r;
}
__device__ __forceinline__ float gex_raw(float x) {   // exp(-pi*x^2), f32
    float u = x * SC;
    return ex2f(-(u * u));
}

__global__ void __launch_bounds__(NTHR, 5)
casa_fused(const float* __restrict__ d, const float* __restrict__ y,
           int NE, int ngroups, float* __restrict__ out) {
    const double NS2 = pk2(NSC2f, NSC2f);

    float accA = 0.f;   // gy + gd   (+0.5)
    float accC = 0.f;   // c1 + c2   (-0.5)
    float accS = 0.f;   // s         (-1)
    const int stride = gridDim.x * blockDim.x;

    for (int g = blockIdx.x * blockDim.x + threadIdx.x; g < ngroups; g += stride) {
        const int base = g << 3;                   // 8 elements per group
        const float4 dA = *reinterpret_cast<const float4*>(d + base);
        const float4 dB = *reinterpret_cast<const float4*>(d + base + 4);
        const float4 yA = *reinterpret_cast<const float4*>(y + base);
        const float4 yB = *reinterpret_cast<const float4*>(y + base + 4);
        const float d8 = __ldg(d + base + 8);
        const float y8 = __ldg(y + base + 8);

        // raw even pairs (k, k+1) straight from the load quads
        double Dp[4], Yp[4];
        Dp[0] = pk2(dA.x, dA.y);  Dp[1] = pk2(dA.z, dA.w);
        Dp[2] = pk2(dB.x, dB.y);  Dp[3] = pk2(dB.z, dB.w);
        Yp[0] = pk2(yA.x, yA.y);  Yp[1] = pk2(yA.z, yA.w);
        Yp[2] = pk2(yB.x, yB.y);  Yp[3] = pk2(yB.z, yB.w);

        // 6 rotating f16x2 accumulators: [even/odd pair] x {A, C, S}
        unsigned hA0 = 0u, hA1 = 0u, hC0 = 0u, hC1 = 0u, hS0 = 0u, hS1 = 0u;

        #pragma unroll
        for (int p = 0; p < 4; p++) {
            const float dn = (p < 3) ? lo2(Dp[p + 1]) : d8;
            const float yn = (p < 3) ? lo2(Yp[p + 1]) : y8;
            const double Dq = pk2(hi2(Dp[p]), dn); // (D_{k+1}, D_{k+2})
            const double Yq = pk2(hi2(Yp[p]), yn);

            // phase 1: all five packed diffs
            const double qG = sub2(Yq, Yp[p]);
            const double qD = sub2(Dq, Dp[p]);
            const double q1 = sub2(Dq, Yp[p]);
            const double q2 = sub2(Dp[p], Yq);
            const double qS = sub2(Dp[p], Yp[p]);
            // phase 2: nv = q * (q * NS2)  (f32x2, two elements each)
            const double nG = mul2(qG, mul2(qG, NS2));
            const double nD = mul2(qD, mul2(qD, NS2));
            const double n1 = mul2(q1, mul2(q1, NS2));
            const double n2 = mul2(q2, mul2(q2, NS2));
            const double nS = mul2(qS, mul2(qS, NS2));
            // phase 3: cvt to half2 (all inputs ready)
            const unsigned cG = h2of(nG);
            const unsigned cD = h2of(nD);
            const unsigned c1 = h2of(n1);
            const unsigned c2 = h2of(n2);
            const unsigned cS = h2of(nS);
            // phase 4: five independent MUFUs, back-to-back
            const unsigned eG = hex2(cG);
            const unsigned eD = hex2(cD);
            const unsigned e1 = hex2(c1);
            const unsigned e2 = hex2(c2);
            const unsigned eS = hex2(cS);
            // phase 5: accumulate into rotating accs (<=4 serial adds each)
            if (p & 1) {
                hA1 = hadd2(hA1, eG); hA1 = hadd2(hA1, eD);
                hC1 = hadd2(hC1, e1); hC1 = hadd2(hC1, e2);
                hS1 = hadd2(hS1, eS);
            } else {
                hA0 = hadd2(hA0, eG); hA0 = hadd2(hA0, eD);
                hC0 = hadd2(hC0, e1); hC0 = hadd2(hC0, e2);
                hS0 = hadd2(hS0, eS);
            }
        }

        // flush per group (each half <= 16, fp16-safe at this granularity)
        accA += h2sum(hadd2(hA0, hA1));
        accC += h2sum(hadd2(hC0, hC1));
        accS += h2sum(hadd2(hS0, hS1));
    }

    // total = 0.5*(A - C) - S
    float acc = fmaf(accA - accC, 0.5f, -accS);

    // block reduce (float)
    #pragma unroll
    for (int o = 16; o; o >>= 1) acc += __shfl_down_sync(0xffffffffu, acc, o);

    __shared__ float sh[NTHR / 32];
    __shared__ bool  s_last;
    const int lane = threadIdx.x & 31;
    const int w    = threadIdx.x >> 5;
    if (lane == 0) sh[w] = acc;
    __syncthreads();
    if (threadIdx.x == 0) {
        float v = 0.f;
        #pragma unroll
        for (int i = 0; i < NTHR / 32; i++) v += sh[i];
        g_partials[blockIdx.x] = v;
        __threadfence();
        unsigned t = atomicAdd(&g_ticket, 1u);
        s_last = (t == (unsigned)gridDim.x - 1u);
    }
    __syncthreads();
    if (!s_last) return;

    // ---- last block: deterministic double-precision finish ----
    const int tid = threadIdx.x;
    double v = 0.0;
    for (int i = tid; i < NBLK; i += NTHR)       // fixed-order per thread
        v += (double)g_partials[i];

    if (tid == 0) {
        for (int k = 8 * ngroups; k < NE; k++) { // tail (empty when NE%8==0)
            float t0 = d[k], t1 = d[k + 1], u0 = y[k], u1 = y[k + 1];
            float a = gex_raw(u1 - u0) + gex_raw(t1 - t0)
                    - gex_raw(t1 - u0) - gex_raw(t0 - u1);
            v += 0.5 * (double)a - (double)gex_raw(t0 - u0);
        }
        v += 0.5 * ((double)gex_raw(d[0] - y[0]) - (double)gex_raw(d[NE] - y[NE]));
        v += (double)NE;
    }

    #pragma unroll
    for (int o = 16; o; o >>= 1) v += __shfl_down_sync(0xffffffffu, v, o);

    __shared__ double shd[NTHR / 32];
    if (lane == 0) shd[w] = v;
    __syncthreads();
    if (tid == 0) {
        double t = 0.0;
        #pragma unroll
        for (int i = 0; i < NTHR / 32; i++) t += shd[i];
        out[0] = (float)t;
        g_ticket = 0;                  // reset for next graph replay
    }
}

extern "C" void kernel_launch(void* const* d_in, const int* in_sizes, int n_in,
                              void* d_out, int out_size) {
    const float* d = (const float*)d_in[0];
    const float* y = (const float*)d_in[1];
    float* out = (float*)d_out;

    const int n  = in_sizes[0];
    const int NE = n - 2;               // 4,000,000 for N = 4,000,002
    const int ngroups = NE / 8;         // 8 consecutive k per group

    casa_fused<<<NBLK, NTHR>>>(d, y, NE, ngroups, out);
}